// round 5
// baseline (speedup 1.0000x reference)
#include <cuda_runtime.h>
#include <math.h>

#define NB 16
#define NS 48
#define SEGLEN 20000
#define ND 256
#define NPIX 65536
#define NVW 512           // 16384 ver bits / 32
#define NOW 2048          // 65536 occupancy bits / 32
#define SIDX 3
#define EIDX 38
#define NSEG (EIDX - SIDX)   // 35
#define NITER 34
#define FLAT (NS*ND)

typedef unsigned long long ull;

// ---- scratch (device globals; no allocations) ----
__device__ unsigned g_histX[NB*NS*ND];
__device__ unsigned g_histY[NB*NS*ND];
__device__ unsigned g_occ[NB*NSEG*NOW];    // unshifted 256x256 occupancy per (b,seg)
__device__ float    g_m[2*NB*NS];          // centroids [axis][b][s]
__device__ int      g_al[2*NB*NS];         // aligned shifts [axis][b][s]
__device__ unsigned g_verseg[NB*NSEG*NVW]; // shifted 128x128 ver bitmaps
__device__ unsigned char g_commit[NB*NS];
__device__ int      g_container[NB*NPIX];
__device__ ull      g_acc[NB][2];          // per-batch s1,s2 partials

// ========== fused hist + occupancy (+ container zeroing) ==========
__global__ void k_hist(const float* __restrict__ ev){
    int s = blockIdx.x, b = blockIdx.y, t = threadIdx.x;   // 512 threads

    // zero this block's slice of g_container
    {
        int base = (b*NS + s) * 1366;
        for(int i = t; i < 1366; i += 512){
            int idx = base + i;
            if(idx < NB*NPIX) g_container[idx] = 0;
        }
    }

    __shared__ unsigned hx[ND][4], hy[ND][4];
    __shared__ unsigned occ[NOW];
    for(int i = t; i < ND*4; i += 512){
        ((unsigned*)hx)[i] = 0;
        ((unsigned*)hy)[i] = 0;
    }
    for(int i = t; i < NOW; i += 512) occ[i] = 0;
    __syncthreads();

    const float4* p4 = reinterpret_cast<const float4*>(
        ev + 2*((size_t)b*(NS*SEGLEN) + (size_t)s*SEGLEN));
    int rep = t & 3;
    bool doOcc = (s >= SIDX && s < EIDX);

    if(doOcc){
        for(int i = t; i < SEGLEN/4; i += 512){
            float4 e0 = p4[i];
            float4 e1 = p4[i + SEGLEN/4];
            int x0 = (int)e0.x, y0 = (int)e0.y;
            int x1 = (int)e0.z, y1 = (int)e0.w;
            int x2 = (int)e1.x, y2 = (int)e1.y;
            int x3 = (int)e1.z, y3 = (int)e1.w;
            atomicAdd(&hx[x0][rep], 1u); atomicAdd(&hy[y0][rep], 1u);
            atomicAdd(&hx[x1][rep], 1u); atomicAdd(&hy[y1][rep], 1u);
            atomicAdd(&hx[x2][rep], 1u); atomicAdd(&hy[y2][rep], 1u);
            atomicAdd(&hx[x3][rep], 1u); atomicAdd(&hy[y3][rep], 1u);
            int i0 = (y0 << 8) + x0, i1 = (y1 << 8) + x1;
            int i2 = (y2 << 8) + x2, i3 = (y3 << 8) + x3;
            atomicOr(&occ[i0 >> 5], 1u << (i0 & 31));
            atomicOr(&occ[i1 >> 5], 1u << (i1 & 31));
            atomicOr(&occ[i2 >> 5], 1u << (i2 & 31));
            atomicOr(&occ[i3 >> 5], 1u << (i3 & 31));
        }
    } else {
        for(int i = t; i < SEGLEN/4; i += 512){
            float4 e0 = p4[i];
            float4 e1 = p4[i + SEGLEN/4];
            atomicAdd(&hx[(int)e0.x][rep], 1u); atomicAdd(&hy[(int)e0.y][rep], 1u);
            atomicAdd(&hx[(int)e0.z][rep], 1u); atomicAdd(&hy[(int)e0.w][rep], 1u);
            atomicAdd(&hx[(int)e1.x][rep], 1u); atomicAdd(&hy[(int)e1.y][rep], 1u);
            atomicAdd(&hx[(int)e1.z][rep], 1u); atomicAdd(&hy[(int)e1.w][rep], 1u);
        }
    }
    __syncthreads();
    if(t < ND){
        g_histX[(b*NS+s)*ND + t] = hx[t][0] + hx[t][1] + hx[t][2] + hx[t][3];
        g_histY[(b*NS+s)*ND + t] = hy[t][0] + hy[t][1] + hy[t][2] + hy[t][3];
    }
    if(doOcc){
        unsigned* dst = g_occ + (size_t)(b*NSEG + (s - SIDX))*NOW;
        for(int i = t; i < NOW; i += 512) dst[i] = occ[i];
    }
}

// ============ stats: cv + separable blur/centroid -> g_m, g_al ============
__global__ void k_stats(){
    int b = blockIdx.x, ax = blockIdx.y, t = threadIdx.x;   // 512 threads
    __shared__ ull a1[512], a2[512];
    __shared__ double R[NS];
    __shared__ float cvs;
    __shared__ float mloc[NS];

    if(b == 0 && ax == 0 && t < NB*2) ((ull*)g_acc)[t] = 0;

    const unsigned* h = (ax ? g_histY : g_histX) + b*FLAT;

    ull s1 = 0, s2 = 0;
    for(int i = t; i < FLAT; i += 512){
        unsigned v = h[i];
        s1 += v; s2 += (ull)v*v;
    }
    a1[t] = s1; a2[t] = s2; __syncthreads();
    for(int o = 256; o; o >>= 1){
        if(t < o){ a1[t] += a1[t+o]; a2[t] += a2[t+o]; }
        __syncthreads();
    }
    if(t == 0){
        double n = (double)FLAT;
        double mean = (double)a1[0] / n;
        double var  = ((double)a2[0] - (double)a1[0]*(double)a1[0]/n) / (n - 1.0);
        cvs = (float)(mean + 3.0*sqrt(var));
    }
    __syncthreads();
    float cv = cvs;

    int w = t >> 5, lane = t & 31;
    for(int r = w; r < NS; r += 16){
        const unsigned* row = h + r*ND;
        double acc = 0.0;
        for(int d = lane; d < ND; d += 32){
            float v = fminf((float)row[d], cv);
            acc += (double)v * (double)d;
        }
        #pragma unroll
        for(int o = 16; o; o >>= 1)
            acc += __shfl_down_sync(0xffffffffu, acc, o);
        if(lane == 0){
            double e0   = (double)fminf((float)row[0],   cv);
            double e1   = (double)fminf((float)row[1],   cv);
            double e254 = (double)fminf((float)row[254], cv);
            double e255 = (double)fminf((float)row[255], cv);
            R[r] = 5.0*acc + 3.0*e0 + e1 - 256.0*e254 - 513.0*e255;
        }
    }
    __syncthreads();
    if(t < NS){
        double s = 0.0;
        int lo = t-2 < 0 ? 0 : t-2, hi = t+2 > NS-1 ? NS-1 : t+2;
        for(int i = lo; i <= hi; i++) s += R[i];
        mloc[t] = (float)((0.04 * s) / (double)SEGLEN);
        g_m[ax*NB*NS + b*NS + t] = mloc[t];
    }
    __syncthreads();
    if(t < NS){
        float st = mloc[SIDX];
        float al = rintf((mloc[t] - st) - (128.0f - st));   // exact ref op order
        g_al[ax*NB*NS + b*NS + t] = (int)al;
    }
}

// ========== shift occupancy -> ver bitmaps ==========
__global__ void k_vshift(){
    int j = blockIdx.x, b = blockIdx.y, t = threadIdx.x;   // 512 threads
    int si = SIDX + j;
    __shared__ unsigned ver[NVW];
    ver[t] = 0;
    __syncthreads();
    int ax = g_al[b*NS + si], ay = g_al[NB*NS + b*NS + si];
    const unsigned* src = g_occ + (size_t)(b*NSEG + j)*NOW;
    #pragma unroll
    for(int k = 0; k < 4; k++){
        int wi = t + k*512;
        unsigned wd = src[wi];
        int xbase = (wi & 7) << 5;
        int y = wi >> 3;
        int ys = min(max(y - ay, 0), 255);
        int yterm = (ys >> 1) << 7;
        while(wd){
            int bp = __ffs(wd) - 1;
            wd &= wd - 1;
            int xs = min(max(xbase + bp - ax, 0), 255);
            int iv = (xs >> 1) + yterm;
            atomicOr(&ver[iv >> 5], 1u << (iv & 31));
        }
    }
    __syncthreads();
    g_verseg[(size_t)(b*NSEG + j)*NVW + t] = ver[t];
}

// ========== scan over ver bitmaps (serial decisions, cheap) ==========
__global__ void k_scan(){
    int b = blockIdx.x, t = threadIdx.x;   // 512 threads == NVW
    int w = t >> 5, lane = t & 31;
    __shared__ unsigned redbuf[16];
    __shared__ unsigned s_tot;
    __shared__ float mm[2][NS];
    __shared__ unsigned char sout[NITER];

    if(t < NS) g_commit[b*NS + t] = 0;
    if(t < 2*NS) ((float*)mm)[t] = g_m[(t/NS)*NB*NS + b*NS + (t%NS)];
    __syncthreads();

    if(t < NITER){
        bool f = false;
        #pragma unroll
        for(int ax = 0; ax < 2; ax++){
            float w10[10], so[10], dd[10];
            for(int i = 0; i < 10; i++){ w10[i] = mm[ax][SIDX + 1 + t + i]; so[i] = w10[i]; }
            for(int i = 1; i < 10; i++){
                float k = so[i]; int j = i - 1;
                while(j >= 0 && so[j] > k){ so[j+1] = so[j]; j--; }
                so[j+1] = k;
            }
            float med = 0.5f*(so[4] + so[5]);
            for(int i = 0; i < 10; i++) dd[i] = fabsf(w10[i] - med);
            float d0 = dd[0];
            for(int i = 1; i < 10; i++){
                float k = dd[i]; int j = i - 1;
                while(j >= 0 && dd[j] > k){ dd[j+1] = dd[j]; j--; }
                dd[j+1] = k;
            }
            float mad = 0.5f*(dd[4] + dd[5]);
            bool fl = (mad == 0.0f) ? (d0 > 0.0f)
                                    : (__fdiv_rn(0.6745f*d0, mad) > 2.0f);
            f = f || fl;
        }
        sout[t] = f ? 1 : 0;
    }
    __syncthreads();

    unsigned va = g_verseg[(size_t)(b*NSEG + 0)*NVW + t];
    unsigned nb = __popc(va);
    #pragma unroll
    for(int o = 16; o; o >>= 1) nb += __shfl_down_sync(0xffffffffu, nb, o);
    if(lane == 0) redbuf[w] = nb;
    __syncthreads();
    if(t == 0){
        unsigned s = 0;
        for(int i = 0; i < 16; i++) s += redbuf[i];
        s_tot = s;
    }
    __syncthreads();
    unsigned cnt = s_tot;
    if(t == 0) g_commit[b*NS + SIDX] = 1;

    for(int si = SIDX + 1; si < EIDX; ++si){
        if(sout[si - SIDX - 1]) continue;
        unsigned wv = g_verseg[(size_t)(b*NSEG + (si - SIDX))*NVW + t];
        unsigned nw = __popc(wv & ~va);
        #pragma unroll
        for(int o = 16; o; o >>= 1) nw += __shfl_down_sync(0xffffffffu, nw, o);
        if(lane == 0) redbuf[w] = nw;
        __syncthreads();
        if(t == 0){
            unsigned s = 0;
            for(int i = 0; i < 16; i++) s += redbuf[i];
            s_tot = s;
        }
        __syncthreads();
        unsigned ni = s_tot;
        unsigned cn = cnt + ni;
        if(__fdiv_rn((float)ni, (float)cn) < 0.1f) break;
        va |= wv;
        cnt = cn;
        if(t == 0) g_commit[b*NS + si] = 1;
        __syncthreads();
    }
}

// ========== container scatter for committed segments ==========
__global__ void k_scatter(const float* __restrict__ ev){
    int si = SIDX + blockIdx.x, b = blockIdx.y, ck = blockIdx.z;
    if(!g_commit[b*NS + si]) return;
    int ax = g_al[b*NS + si], ay = g_al[NB*NS + b*NS + si];
    const float4* p = reinterpret_cast<const float4*>(
        ev + 2*((size_t)b*(NS*SEGLEN) + (size_t)si*SEGLEN));
    int* cont = g_container + b*NPIX;
    int lo = ck * (SEGLEN/8), hi = lo + (SEGLEN/8);
    for(int i = lo + threadIdx.x; i < hi; i += blockDim.x){
        float4 e = p[i];
        {
            int xs = min(max((int)e.x - ax, 0), 255);
            int ys = min(max((int)e.y - ay, 0), 255);
            atomicAdd(&cont[xs + (ys << 8)], 1);
        }
        {
            int xs = min(max((int)e.z - ax, 0), 255);
            int ys = min(max((int)e.w - ay, 0), 255);
            atomicAdd(&cont[xs + (ys << 8)], 1);
        }
    }
}

// ========== final stats ==========
__global__ void k_fstat(){
    int pb = blockIdx.x, b = blockIdx.y, t = threadIdx.x;
    const int* c = g_container + b*NPIX + pb*(NPIX/16);
    ull s1 = 0, s2 = 0;
    for(int i = t; i < NPIX/16; i += 512){
        unsigned v = (unsigned)c[i];
        s1 += v; s2 += (ull)v*v;
    }
    __shared__ ull a1[512], a2[512];
    a1[t] = s1; a2[t] = s2; __syncthreads();
    for(int o = 256; o; o >>= 1){
        if(t < o){ a1[t] += a1[t+o]; a2[t] += a2[t+o]; }
        __syncthreads();
    }
    if(t == 0){
        atomicAdd(&g_acc[b][0], a1[0]);
        atomicAdd(&g_acc[b][1], a2[0]);
    }
}

// ========== final normalize ==========
__global__ void k_fnorm(float* __restrict__ out){
    int idx = blockIdx.x*blockDim.x + threadIdx.x;
    int b = idx >> 16;
    __shared__ float scv;
    if(threadIdx.x == 0){
        double n = (double)NPIX;
        double s1 = (double)g_acc[b][0], s2 = (double)g_acc[b][1];
        double mean = s1 / n;
        double var  = (s2 - s1*s1/n) / (n - 1.0);
        scv = (float)(mean + 3.0*sqrt(var));
    }
    __syncthreads();
    float cv = scv;
    float v = fminf((float)g_container[idx], cv);
    out[idx] = __fdiv_rn(v, cv);
}

// ========== launch ==========
extern "C" void kernel_launch(void* const* d_in, const int* in_sizes, int n_in,
                              void* d_out, int out_size){
    const float* ev = (const float*)d_in[0];
    float* out = (float*)d_out;
    (void)in_sizes; (void)n_in; (void)out_size;

    { dim3 g(NS, NB);   k_hist  <<<g, 512>>>(ev); }
    { dim3 g(NB, 2);    k_stats <<<g, 512>>>(); }
    { dim3 g(NSEG, NB); k_vshift<<<g, 512>>>(); }
    k_scan<<<NB, NVW>>>();
    { dim3 g(NSEG, NB, 4); k_scatter<<<g, 512>>>(ev); }
    { dim3 g(16, NB);   k_fstat <<<g, 512>>>(); }
    k_fnorm<<<NB*NPIX/1024, 1024>>>(out);
}